// round 1
// baseline (speedup 1.0000x reference)
#include <cuda_runtime.h>

// Problem constants (fixed by the reference module)
#define N_TOK 10368      // 18*24*24 tokens
#define CDIM  256        // channels
#define HDIM  128        // c/2
#define NCHUNK 81        // N_TOK / 128 partial-G chunks

// Scratch (no cudaMalloc allowed)
__device__ float g_F[CDIM * N_TOK];              // rows 0..127 = Fi, 128..255 = Fj
__device__ float g_Gpart[NCHUNK * HDIM * CDIM];  // per-chunk partial G
__device__ float g_G[HDIM * CDIM];               // G[p][q] = (1/N) sum_n Fj[p][n] feat[q][n]

// ---------------------------------------------------------------------------
// Kernel A:  F[m,n] = sum_k W[m,k] * feat[k,n] + b[m]
//   blockIdx.y = 0 -> (Wi, bi) rows 0..127 ; = 1 -> (Wj, bj) rows 128..255
//   BM=128, BN=64, BK=16, 256 threads, 8x4 register tile
// ---------------------------------------------------------------------------
__global__ __launch_bounds__(256)
void k_gemm_F(const float* __restrict__ feat,
              const float* __restrict__ Wi, const float* __restrict__ bi,
              const float* __restrict__ Wj, const float* __restrict__ bj)
{
    constexpr int BM = 128, BN = 64, BK = 16, TM = 8, TN = 4;
    __shared__ float Ws[BK][BM];
    __shared__ float As[BK][BN + 4];

    const float* W  = blockIdx.y ? Wj : Wi;
    const float* bv = blockIdx.y ? bj : bi;
    const int n0  = blockIdx.x * BN;
    const int tid = threadIdx.x;
    const int tm0 = (tid / (BN / TN)) * TM;   // (tid/16)*8
    const int tn0 = (tid % (BN / TN)) * TN;   // (tid%16)*4

    float acc[TM][TN] = {};

    for (int k0 = 0; k0 < CDIM; k0 += BK) {
        // W tile: BM x BK, transposed into Ws[k][m]
        #pragma unroll
        for (int it = 0; it < 2; ++it) {
            int idx = (it * 256 + tid) * 4;
            int m = idx >> 4;       // / BK
            int k = idx & 15;       // % BK (multiple of 4)
            float4 v = *(const float4*)(W + m * CDIM + k0 + k);
            Ws[k + 0][m] = v.x; Ws[k + 1][m] = v.y;
            Ws[k + 2][m] = v.z; Ws[k + 3][m] = v.w;
        }
        // feat tile: BK x BN (1024 elems = one float4 pass)
        {
            int idx = tid * 4;
            int k = idx >> 6;       // / BN
            int n = idx & 63;       // % BN
            *(float4*)(&As[k][n]) =
                *(const float4*)(feat + (size_t)(k0 + k) * N_TOK + n0 + n);
        }
        __syncthreads();

        #pragma unroll
        for (int k = 0; k < BK; ++k) {
            float a[TM], b[TN];
            *(float4*)(a)     = *(const float4*)(&Ws[k][tm0]);
            *(float4*)(a + 4) = *(const float4*)(&Ws[k][tm0 + 4]);
            *(float4*)(b)     = *(const float4*)(&As[k][tn0]);
            #pragma unroll
            for (int i = 0; i < TM; ++i)
                #pragma unroll
                for (int j = 0; j < TN; ++j)
                    acc[i][j] = fmaf(a[i], b[j], acc[i][j]);
        }
        __syncthreads();
    }

    const int mg = blockIdx.y * BM + tm0;
    #pragma unroll
    for (int i = 0; i < TM; ++i) {
        float bb = bv[tm0 + i];
        float4 r = make_float4(acc[i][0] + bb, acc[i][1] + bb,
                               acc[i][2] + bb, acc[i][3] + bb);
        *(float4*)(&g_F[(size_t)(mg + i) * N_TOK + n0 + tn0]) = r;
    }
}

// ---------------------------------------------------------------------------
// Kernel B:  Gpart[z][p][q] = sum_{n in chunk z (128 tokens)} Fj[p][n]*feat[q][n]
//   grid (CDIM/64, HDIM/64, 81), 256 threads, 4x4 register tile
//   Deterministic (no float atomics); reduced in k_reduce_G.
// ---------------------------------------------------------------------------
__global__ __launch_bounds__(256)
void k_gemm_Gpart(const float* __restrict__ feat)
{
    constexpr int BP = 64, BQ = 64, NK = 32, TP = 4, TQ = 4, CH = 128;
    __shared__ float sP[NK][BP + 1];
    __shared__ float sQ[NK][BQ + 1];

    const int q0 = blockIdx.x * BQ;
    const int p0 = blockIdx.y * BP;
    const int nbase = blockIdx.z * CH;
    const int tid = threadIdx.x;
    const int tp0 = (tid / (BQ / TQ)) * TP;   // (tid/16)*4
    const int tq0 = (tid % (BQ / TQ)) * TQ;   // (tid%16)*4
    const float* Fj = g_F + (size_t)HDIM * N_TOK;

    float acc[TP][TQ] = {};

    for (int nk0 = 0; nk0 < CH; nk0 += NK) {
        #pragma unroll
        for (int it = 0; it < 2; ++it) {
            int idx = (it * 256 + tid) * 4;
            int r = idx >> 5;     // / NK : local p (and q) row 0..63
            int n = idx & 31;     // % NK (multiple of 4)
            float4 v = *(const float4*)(Fj + (size_t)(p0 + r) * N_TOK + nbase + nk0 + n);
            sP[n + 0][r] = v.x; sP[n + 1][r] = v.y;
            sP[n + 2][r] = v.z; sP[n + 3][r] = v.w;
            float4 w = *(const float4*)(feat + (size_t)(q0 + r) * N_TOK + nbase + nk0 + n);
            sQ[n + 0][r] = w.x; sQ[n + 1][r] = w.y;
            sQ[n + 2][r] = w.z; sQ[n + 3][r] = w.w;
        }
        __syncthreads();

        #pragma unroll
        for (int n = 0; n < NK; ++n) {
            float a[TP], b[TQ];
            #pragma unroll
            for (int i = 0; i < TP; ++i) a[i] = sP[n][tp0 + i];
            #pragma unroll
            for (int j = 0; j < TQ; ++j) b[j] = sQ[n][tq0 + j];
            #pragma unroll
            for (int i = 0; i < TP; ++i)
                #pragma unroll
                for (int j = 0; j < TQ; ++j)
                    acc[i][j] = fmaf(a[i], b[j], acc[i][j]);
        }
        __syncthreads();
    }

    float* outp = g_Gpart + (size_t)blockIdx.z * HDIM * CDIM;
    #pragma unroll
    for (int i = 0; i < TP; ++i) {
        float4 r = make_float4(acc[i][0], acc[i][1], acc[i][2], acc[i][3]);
        *(float4*)(&outp[(p0 + tp0 + i) * CDIM + q0 + tq0]) = r;
    }
}

// ---------------------------------------------------------------------------
// Kernel B2: G = (1/N) * sum over 81 partials
// ---------------------------------------------------------------------------
__global__ __launch_bounds__(256)
void k_reduce_G()
{
    int idx = blockIdx.x * 256 + threadIdx.x;   // 0 .. 32767
    float s = 0.f;
    #pragma unroll 3
    for (int c = 0; c < NCHUNK; ++c)
        s += g_Gpart[(size_t)c * HDIM * CDIM + idx];
    g_G[idx] = s * (1.0f / N_TOK);
}

// ---------------------------------------------------------------------------
// Kernel C:  out[q,n] = feat[q,n] + sum_p G[p][q] * Fi[p][n]
//   GEMM M=256 (q), K=128 (p), N=10368 ; same tiling as kernel A
// ---------------------------------------------------------------------------
__global__ __launch_bounds__(256)
void k_gemm_out(const float* __restrict__ feat, float* __restrict__ outp)
{
    constexpr int BM = 128, BN = 64, BK = 16, TM = 8, TN = 4;
    __shared__ float Gs[BK][BM];
    __shared__ float Fs[BK][BN + 4];

    const int n0 = blockIdx.x * BN;
    const int m0 = blockIdx.y * BM;   // q offset
    const int tid = threadIdx.x;
    const int tm0 = (tid / (BN / TN)) * TM;
    const int tn0 = (tid % (BN / TN)) * TN;

    float acc[TM][TN] = {};

    for (int k0 = 0; k0 < HDIM; k0 += BK) {
        // G tile: Gs[k][m] = G[(k0+k)][m0+m]  (G is [p][q] row-major -> direct, no transpose)
        #pragma unroll
        for (int it = 0; it < 2; ++it) {
            int idx = (it * 256 + tid) * 4;
            int k = idx >> 7;      // / BM
            int m = idx & 127;     // % BM (multiple of 4)
            *(float4*)(&Gs[k][m]) = *(const float4*)(&g_G[(k0 + k) * CDIM + m0 + m]);
        }
        // Fi tile
        {
            int idx = tid * 4;
            int k = idx >> 6;
            int n = idx & 63;
            *(float4*)(&Fs[k][n]) =
                *(const float4*)(&g_F[(size_t)(k0 + k) * N_TOK + n0 + n]);
        }
        __syncthreads();

        #pragma unroll
        for (int k = 0; k < BK; ++k) {
            float a[TM], b[TN];
            *(float4*)(a)     = *(const float4*)(&Gs[k][tm0]);
            *(float4*)(a + 4) = *(const float4*)(&Gs[k][tm0 + 4]);
            *(float4*)(b)     = *(const float4*)(&Fs[k][tn0]);
            #pragma unroll
            for (int i = 0; i < TM; ++i)
                #pragma unroll
                for (int j = 0; j < TN; ++j)
                    acc[i][j] = fmaf(a[i], b[j], acc[i][j]);
        }
        __syncthreads();
    }

    #pragma unroll
    for (int i = 0; i < TM; ++i) {
        size_t off = (size_t)(m0 + tm0 + i) * N_TOK + n0 + tn0;
        float4 f = *(const float4*)(&feat[off]);
        float4 r = make_float4(acc[i][0] + f.x, acc[i][1] + f.y,
                               acc[i][2] + f.z, acc[i][3] + f.w);
        *(float4*)(&outp[off]) = r;
    }
}

// ---------------------------------------------------------------------------
extern "C" void kernel_launch(void* const* d_in, const int* in_sizes, int n_in,
                              void* d_out, int out_size)
{
    const float* feat = (const float*)d_in[0];   // [256, 10368]
    const float* Wi   = (const float*)d_in[1];   // [128, 256]
    const float* bi   = (const float*)d_in[2];   // [128]
    const float* Wj   = (const float*)d_in[3];   // [128, 256]
    const float* bj   = (const float*)d_in[4];   // [128]
    float* outp = (float*)d_out;                  // [256, 10368]

    k_gemm_F    <<<dim3(N_TOK / 64, 2),            256>>>(feat, Wi, bi, Wj, bj);
    k_gemm_Gpart<<<dim3(CDIM / 64, HDIM / 64, NCHUNK), 256>>>(feat);
    k_reduce_G  <<<(HDIM * CDIM) / 256,            256>>>();
    k_gemm_out  <<<dim3(N_TOK / 64, 2),            256>>>(feat, outp);
}